// round 2
// baseline (speedup 1.0000x reference)
#include <cuda_runtime.h>

// Problem constants
#define BB   8
#define SS   1024
#define CC   768
#define HH   12
#define HDM  64
#define BHN  (BB*HH)     // 96
#define QQ   32

// Scratch (static device allocations — no cudaMalloc allowed)
__device__ float g_q[BHN*SS*HDM];                 // (bh, s, d)
__device__ float g_k[BHN*SS*HDM];
__device__ float g_v[BHN*SS*HDM];
__device__ float g_relh[BHN*QQ*QQ*QQ];            // (bh, i, j, ti)
__device__ float g_relw[BHN*QQ*QQ*QQ];            // (bh, i, j, tj)
__device__ float g_attn[(size_t)BHN*SS*SS];       // (bh, x, y)  ~403 MB
__device__ float g_ctx[BB*SS*CC];                 // (b, s, h*64+d)

// ---------------------------------------------------------------------------
// Kernel 1: qkv = x @ w_qkv^T, scattered into q/k/v with (bh, s, d) layout.
// 128x128 block tile, BK=8, 8x8 per thread, 256 threads.
// ---------------------------------------------------------------------------
__global__ __launch_bounds__(256) void k_qkv(const float* __restrict__ X,
                                             const float* __restrict__ W) {
    __shared__ __align__(16) float As[8][128];
    __shared__ __align__(16) float Bs[8][128];
    const int tid = threadIdx.x;
    const int bm = blockIdx.y * 128;
    const int bn = blockIdx.x * 128;
    const int lr = tid >> 1;            // 0..127
    const int lc = (tid & 1) * 4;       // 0 or 4
    const int tx = tid & 15;            // 0..15  (N)
    const int ty = tid >> 4;            // 0..15  (M)
    float acc[8][8];
#pragma unroll
    for (int i = 0; i < 8; i++)
#pragma unroll
        for (int j = 0; j < 8; j++) acc[i][j] = 0.f;

    for (int k0 = 0; k0 < CC; k0 += 8) {
        float4 a = *(const float4*)(X + (size_t)(bm + lr) * CC + k0 + lc);
        As[lc+0][lr] = a.x; As[lc+1][lr] = a.y; As[lc+2][lr] = a.z; As[lc+3][lr] = a.w;
        float4 b = *(const float4*)(W + (size_t)(bn + lr) * CC + k0 + lc);
        Bs[lc+0][lr] = b.x; Bs[lc+1][lr] = b.y; Bs[lc+2][lr] = b.z; Bs[lc+3][lr] = b.w;
        __syncthreads();
#pragma unroll
        for (int k = 0; k < 8; k++) {
            float af[8], bf[8];
            *(float4*)(af)     = *(const float4*)(&As[k][ty*8]);
            *(float4*)(af + 4) = *(const float4*)(&As[k][ty*8 + 4]);
            *(float4*)(bf)     = *(const float4*)(&Bs[k][tx*8]);
            *(float4*)(bf + 4) = *(const float4*)(&Bs[k][tx*8 + 4]);
#pragma unroll
            for (int i = 0; i < 8; i++)
#pragma unroll
                for (int j = 0; j < 8; j++)
                    acc[i][j] += af[i] * bf[j];
        }
        __syncthreads();
    }

#pragma unroll
    for (int i = 0; i < 8; i++) {
        const int m = bm + ty*8 + i;
        const int b = m >> 10, s = m & 1023;
#pragma unroll
        for (int j = 0; j < 8; j++) {
            const int n = bn + tx*8 + j;
            const int part = n / CC;           // 0=q,1=k,2=v
            const int rem  = n - part * CC;
            const int h = rem >> 6, d = rem & 63;
            float* dst = (part == 0) ? g_q : ((part == 1) ? g_k : g_v);
            dst[((size_t)(b * HH + h) * SS + s) * HDM + d] = acc[i][j];
        }
    }
}

// ---------------------------------------------------------------------------
// Kernel 2: decomposed rel-pos tables.
// rel_h[bh,i,j,ti] = sum_d q[bh,i*32+j,d] * rel_pos_h[i-ti+31, d]
// rel_w[bh,i,j,tj] = sum_d q[bh,i*32+j,d] * rel_pos_w[j-tj+31, d]
// one block per (bh, i)
// ---------------------------------------------------------------------------
__global__ __launch_bounds__(256) void k_rel(const float* __restrict__ rph,
                                             const float* __restrict__ rpw) {
    __shared__ float Qs[32][64];
    __shared__ float Rh[32][64];
    __shared__ float Rw[63][64];
    const int bh = blockIdx.x;
    const int qi = blockIdx.y;
    const int tid = threadIdx.x;
    const float* qp = g_q + ((size_t)bh * SS + (size_t)qi * QQ) * HDM;

    for (int idx = tid; idx < 32 * 64; idx += 256) {
        const int r = idx >> 6, d = idx & 63;
        Qs[r][d] = qp[(size_t)r * HDM + d];
        Rh[r][d] = rph[(size_t)(qi - r + 31) * HDM + d];
    }
    for (int idx = tid; idx < 63 * 64; idx += 256) {
        Rw[idx >> 6][idx & 63] = rpw[idx];
    }
    __syncthreads();

    float* relh = g_relh + ((size_t)bh * QQ + qi) * QQ * QQ;
    float* relw = g_relw + ((size_t)bh * QQ + qi) * QQ * QQ;
    for (int p = tid; p < 32 * 32; p += 256) {
        const int j = p >> 5, t = p & 31;
        const float* qrow = Qs[j];
        const float* rhr  = Rh[t];
        const float* rwr  = Rw[j - t + 31];
        float sh = 0.f, sw = 0.f;
#pragma unroll
        for (int d = 0; d < 64; d++) {
            sh += qrow[d] * rhr[d];
            sw += qrow[d] * rwr[d];
        }
        relh[(size_t)j * QQ + t] = sh;
        relw[(size_t)j * QQ + t] = sw;
    }
}

// ---------------------------------------------------------------------------
// Kernel 3: attn[bh,x,y] = 0.125 * q[bh,x,:]·k[bh,y,:] + relh + relw
// batched 1024x1024x64 GEMM, 128x128 tiles, grid (8,8,96)
// ---------------------------------------------------------------------------
__global__ __launch_bounds__(256) void k_scores() {
    __shared__ __align__(16) float As[8][128];
    __shared__ __align__(16) float Bs[8][128];
    const int tid = threadIdx.x;
    const int bh = blockIdx.z;
    const int bm = blockIdx.y * 128;
    const int bn = blockIdx.x * 128;
    const float* Qp = g_q + (size_t)bh * SS * HDM;
    const float* Kp = g_k + (size_t)bh * SS * HDM;
    const int lr = tid >> 1;
    const int lc = (tid & 1) * 4;
    const int tx = tid & 15, ty = tid >> 4;
    float acc[8][8];
#pragma unroll
    for (int i = 0; i < 8; i++)
#pragma unroll
        for (int j = 0; j < 8; j++) acc[i][j] = 0.f;

    for (int k0 = 0; k0 < HDM; k0 += 8) {
        float4 a = *(const float4*)(Qp + (size_t)(bm + lr) * HDM + k0 + lc);
        As[lc+0][lr] = a.x; As[lc+1][lr] = a.y; As[lc+2][lr] = a.z; As[lc+3][lr] = a.w;
        float4 b = *(const float4*)(Kp + (size_t)(bn + lr) * HDM + k0 + lc);
        Bs[lc+0][lr] = b.x; Bs[lc+1][lr] = b.y; Bs[lc+2][lr] = b.z; Bs[lc+3][lr] = b.w;
        __syncthreads();
#pragma unroll
        for (int k = 0; k < 8; k++) {
            float af[8], bf[8];
            *(float4*)(af)     = *(const float4*)(&As[k][ty*8]);
            *(float4*)(af + 4) = *(const float4*)(&As[k][ty*8 + 4]);
            *(float4*)(bf)     = *(const float4*)(&Bs[k][tx*8]);
            *(float4*)(bf + 4) = *(const float4*)(&Bs[k][tx*8 + 4]);
#pragma unroll
            for (int i = 0; i < 8; i++)
#pragma unroll
                for (int j = 0; j < 8; j++)
                    acc[i][j] += af[i] * bf[j];
        }
        __syncthreads();
    }

    const float* rh = g_relh + (size_t)bh * QQ * QQ * QQ;
    const float* rw = g_relw + (size_t)bh * QQ * QQ * QQ;
    float* out = g_attn + (size_t)bh * SS * SS;
#pragma unroll
    for (int i = 0; i < 8; i++) {
        const int x = bm + ty*8 + i;
        const int qi = x >> 5, qj = x & 31;
        const float* rhrow = rh + ((size_t)qi * QQ + qj) * QQ;
        const float* rwrow = rw + ((size_t)qi * QQ + qj) * QQ;
#pragma unroll
        for (int j = 0; j < 8; j++) {
            const int y = bn + tx*8 + j;
            const int ti = y >> 5, tj = y & 31;
            out[(size_t)x * SS + y] = acc[i][j] * 0.125f + rhrow[ti] + rwrow[tj];
        }
    }
}

// ---------------------------------------------------------------------------
// Kernel 4: row softmax over 1024, one block per row, float4 per thread.
// ---------------------------------------------------------------------------
__global__ __launch_bounds__(256) void k_softmax() {
    __shared__ float rm[8];
    __shared__ float rs[8];
    const size_t row = blockIdx.x;
    float* p = g_attn + row * SS;
    const int tid = threadIdx.x;
    float4 v = reinterpret_cast<const float4*>(p)[tid];

    float m = fmaxf(fmaxf(v.x, v.y), fmaxf(v.z, v.w));
#pragma unroll
    for (int o = 16; o; o >>= 1) m = fmaxf(m, __shfl_xor_sync(0xffffffffu, m, o));
    if ((tid & 31) == 0) rm[tid >> 5] = m;
    __syncthreads();
    float gm = rm[0];
#pragma unroll
    for (int w = 1; w < 8; w++) gm = fmaxf(gm, rm[w]);

    v.x = __expf(v.x - gm);
    v.y = __expf(v.y - gm);
    v.z = __expf(v.z - gm);
    v.w = __expf(v.w - gm);
    float s = v.x + v.y + v.z + v.w;
#pragma unroll
    for (int o = 16; o; o >>= 1) s += __shfl_xor_sync(0xffffffffu, s, o);
    if ((tid & 31) == 0) rs[tid >> 5] = s;
    __syncthreads();
    float gs = rs[0];
#pragma unroll
    for (int w = 1; w < 8; w++) gs += rs[w];

    const float inv = 1.0f / gs;
    v.x *= inv; v.y *= inv; v.z *= inv; v.w *= inv;
    reinterpret_cast<float4*>(p)[tid] = v;
}

// ---------------------------------------------------------------------------
// Kernel 5: ctx[b,s,h*64+d] = sum_y attn[bh,s,y] * v[bh,y,d]
// per bh: 1024x64x1024 GEMM. BM=128, BN=64, BK=16, 8x4 per thread.
// ---------------------------------------------------------------------------
__global__ __launch_bounds__(256) void k_av() {
    __shared__ __align__(16) float As[16][128];
    __shared__ __align__(16) float Bs[16][64];
    const int tid = threadIdx.x;
    const int bh = blockIdx.y;
    const int bm = blockIdx.x * 128;
    const float* Ap = g_attn + (size_t)bh * SS * SS;
    const float* Vp = g_v + (size_t)bh * SS * HDM;
    const int lrA = tid >> 1;             // 0..127
    const int lcA = (tid & 1) * 8;        // 0 or 8
    const int lrB = tid >> 4;             // 0..15
    const int lcB = (tid & 15) * 4;       // 0..60
    const int tx = tid & 15;              // N: tx*4
    const int ty = tid >> 4;              // M: ty*8
    float acc[8][4];
#pragma unroll
    for (int i = 0; i < 8; i++)
#pragma unroll
        for (int j = 0; j < 4; j++) acc[i][j] = 0.f;

    for (int k0 = 0; k0 < SS; k0 += 16) {
        const float* arow = Ap + (size_t)(bm + lrA) * SS + k0 + lcA;
        float4 a0 = *(const float4*)(arow);
        float4 a1 = *(const float4*)(arow + 4);
        As[lcA+0][lrA] = a0.x; As[lcA+1][lrA] = a0.y; As[lcA+2][lrA] = a0.z; As[lcA+3][lrA] = a0.w;
        As[lcA+4][lrA] = a1.x; As[lcA+5][lrA] = a1.y; As[lcA+6][lrA] = a1.z; As[lcA+7][lrA] = a1.w;
        *(float4*)(&Bs[lrB][lcB]) = *(const float4*)(Vp + (size_t)(k0 + lrB) * HDM + lcB);
        __syncthreads();
#pragma unroll
        for (int k = 0; k < 16; k++) {
            float af[8], bf[4];
            *(float4*)(af)     = *(const float4*)(&As[k][ty*8]);
            *(float4*)(af + 4) = *(const float4*)(&As[k][ty*8 + 4]);
            *(float4*)(bf)     = *(const float4*)(&Bs[k][tx*4]);
#pragma unroll
            for (int i = 0; i < 8; i++)
#pragma unroll
                for (int j = 0; j < 4; j++)
                    acc[i][j] += af[i] * bf[j];
        }
        __syncthreads();
    }

    const int b = bh / HH, h = bh % HH;
#pragma unroll
    for (int i = 0; i < 8; i++) {
        const int s = bm + ty*8 + i;
        float* dst = g_ctx + (size_t)(b * SS + s) * CC + h * HDM + tx * 4;
        *(float4*)dst = make_float4(acc[i][0], acc[i][1], acc[i][2], acc[i][3]);
    }
}

// ---------------------------------------------------------------------------
// Kernel 6: out = ctx @ w_out^T + b_out. M=8192, N=768, K=768.
// ---------------------------------------------------------------------------
__global__ __launch_bounds__(256) void k_proj(const float* __restrict__ W,
                                              const float* __restrict__ bias,
                                              float* __restrict__ out) {
    __shared__ __align__(16) float As[8][128];
    __shared__ __align__(16) float Bs[8][128];
    const int tid = threadIdx.x;
    const int bm = blockIdx.y * 128;
    const int bn = blockIdx.x * 128;
    const int lr = tid >> 1;
    const int lc = (tid & 1) * 4;
    const int tx = tid & 15, ty = tid >> 4;
    float acc[8][8];
#pragma unroll
    for (int i = 0; i < 8; i++)
#pragma unroll
        for (int j = 0; j < 8; j++) acc[i][j] = 0.f;

    for (int k0 = 0; k0 < CC; k0 += 8) {
        float4 a = *(const float4*)(g_ctx + (size_t)(bm + lr) * CC + k0 + lc);
        As[lc+0][lr] = a.x; As[lc+1][lr] = a.y; As[lc+2][lr] = a.z; As[lc+3][lr] = a.w;
        float4 b = *(const float4*)(W + (size_t)(bn + lr) * CC + k0 + lc);
        Bs[lc+0][lr] = b.x; Bs[lc+1][lr] = b.y; Bs[lc+2][lr] = b.z; Bs[lc+3][lr] = b.w;
        __syncthreads();
#pragma unroll
        for (int k = 0; k < 8; k++) {
            float af[8], bf[8];
            *(float4*)(af)     = *(const float4*)(&As[k][ty*8]);
            *(float4*)(af + 4) = *(const float4*)(&As[k][ty*8 + 4]);
            *(float4*)(bf)     = *(const float4*)(&Bs[k][tx*8]);
            *(float4*)(bf + 4) = *(const float4*)(&Bs[k][tx*8 + 4]);
#pragma unroll
            for (int i = 0; i < 8; i++)
#pragma unroll
                for (int j = 0; j < 8; j++)
                    acc[i][j] += af[i] * bf[j];
        }
        __syncthreads();
    }

#pragma unroll
    for (int i = 0; i < 8; i++) {
        const int m = bm + ty*8 + i;
#pragma unroll
        for (int j = 0; j < 8; j++) {
            const int n = bn + tx*8 + j;
            out[(size_t)m * CC + n] = acc[i][j] + bias[n];
        }
    }
}

// ---------------------------------------------------------------------------
extern "C" void kernel_launch(void* const* d_in, const int* in_sizes, int n_in,
                              void* d_out, int out_size) {
    const float* x     = (const float*)d_in[0];
    const float* w_qkv = (const float*)d_in[1];
    const float* w_out = (const float*)d_in[2];
    const float* b_out = (const float*)d_in[3];
    const float* rph   = (const float*)d_in[4];
    const float* rpw   = (const float*)d_in[5];
    float* out = (float*)d_out;

    k_qkv   <<<dim3(2304/128, 8192/128), 256>>>(x, w_qkv);
    k_rel   <<<dim3(BHN, QQ), 256>>>(rph, rpw);
    k_scores<<<dim3(8, 8, BHN), 256>>>();
    k_softmax<<<dim3(BHN * SS), 256>>>();
    k_av    <<<dim3(8, BHN), 256>>>();
    k_proj  <<<dim3(768/128, 8192/128), 256>>>(w_out, b_out, out);
}

// round 3
// speedup vs baseline: 1.0036x; 1.0036x over previous
#include <cuda_runtime.h>

// Problem constants
#define BB   8
#define SS   1024
#define CC   768
#define HH   12
#define HDM  64
#define BHN  (BB*HH)     // 96
#define QQ   32

// Scratch (static device allocations — no cudaMalloc allowed)
__device__ float g_q[BHN*SS*HDM];                 // (bh, s, d)
__device__ float g_k[BHN*SS*HDM];
__device__ float g_v[BHN*SS*HDM];
__device__ float g_relh[BHN*QQ*QQ*QQ];            // (bh, i, j, ti)
__device__ float g_relw[BHN*QQ*QQ*QQ];            // (bh, i, j, tj)
__device__ float g_attn[(size_t)BHN*SS*SS];       // (bh, x, y)  ~403 MB
__device__ float g_ctx[BB*SS*CC];                 // (b, s, h*64+d)

// ---------------------------------------------------------------------------
// Kernel 1: qkv = x @ w_qkv^T, scattered into q/k/v with (bh, s, d) layout.
// 128x128 block tile, BK=8, 8x8 per thread, 256 threads.
// ---------------------------------------------------------------------------
__global__ __launch_bounds__(256) void k_qkv(const float* __restrict__ X,
                                             const float* __restrict__ W) {
    __shared__ __align__(16) float As[8][128];
    __shared__ __align__(16) float Bs[8][128];
    const int tid = threadIdx.x;
    const int bm = blockIdx.y * 128;
    const int bn = blockIdx.x * 128;
    const int lr = tid >> 1;            // 0..127
    const int lc = (tid & 1) * 4;       // 0 or 4
    const int tx = tid & 15;            // 0..15  (N)
    const int ty = tid >> 4;            // 0..15  (M)
    float acc[8][8];
#pragma unroll
    for (int i = 0; i < 8; i++)
#pragma unroll
        for (int j = 0; j < 8; j++) acc[i][j] = 0.f;

    for (int k0 = 0; k0 < CC; k0 += 8) {
        float4 a = *(const float4*)(X + (size_t)(bm + lr) * CC + k0 + lc);
        As[lc+0][lr] = a.x; As[lc+1][lr] = a.y; As[lc+2][lr] = a.z; As[lc+3][lr] = a.w;
        float4 b = *(const float4*)(W + (size_t)(bn + lr) * CC + k0 + lc);
        Bs[lc+0][lr] = b.x; Bs[lc+1][lr] = b.y; Bs[lc+2][lr] = b.z; Bs[lc+3][lr] = b.w;
        __syncthreads();
#pragma unroll
        for (int k = 0; k < 8; k++) {
            float af[8], bf[8];
            *(float4*)(af)     = *(const float4*)(&As[k][ty*8]);
            *(float4*)(af + 4) = *(const float4*)(&As[k][ty*8 + 4]);
            *(float4*)(bf)     = *(const float4*)(&Bs[k][tx*8]);
            *(float4*)(bf + 4) = *(const float4*)(&Bs[k][tx*8 + 4]);
#pragma unroll
            for (int i = 0; i < 8; i++)
#pragma unroll
                for (int j = 0; j < 8; j++)
                    acc[i][j] += af[i] * bf[j];
        }
        __syncthreads();
    }

#pragma unroll
    for (int i = 0; i < 8; i++) {
        const int m = bm + ty*8 + i;
        const int b = m >> 10, s = m & 1023;
#pragma unroll
        for (int j = 0; j < 8; j++) {
            const int n = bn + tx*8 + j;
            const int part = n / CC;           // 0=q,1=k,2=v
            const int rem  = n - part * CC;
            const int h = rem >> 6, d = rem & 63;
            float* dst = (part == 0) ? g_q : ((part == 1) ? g_k : g_v);
            dst[((size_t)(b * HH + h) * SS + s) * HDM + d] = acc[i][j];
        }
    }
}

// ---------------------------------------------------------------------------
// Kernel 2: decomposed rel-pos tables.
// rel_h[bh,i,j,ti] = sum_d q[bh,i*32+j,d] * rel_pos_h[i-ti+31, d]
// rel_w[bh,i,j,tj] = sum_d q[bh,i*32+j,d] * rel_pos_w[j-tj+31, d]
// one block per (bh, i)
// ---------------------------------------------------------------------------
__global__ __launch_bounds__(256) void k_rel(const float* __restrict__ rph,
                                             const float* __restrict__ rpw) {
    __shared__ float Qs[32][64];
    __shared__ float Rh[32][64];
    __shared__ float Rw[63][64];
    const int bh = blockIdx.x;
    const int qi = blockIdx.y;
    const int tid = threadIdx.x;
    const float* qp = g_q + ((size_t)bh * SS + (size_t)qi * QQ) * HDM;

    for (int idx = tid; idx < 32 * 64; idx += 256) {
        const int r = idx >> 6, d = idx & 63;
        Qs[r][d] = qp[(size_t)r * HDM + d];
        Rh[r][d] = rph[(size_t)(qi - r + 31) * HDM + d];
    }
    for (int idx = tid; idx < 63 * 64; idx += 256) {
        Rw[idx >> 6][idx & 63] = rpw[idx];
    }
    __syncthreads();

    float* relh = g_relh + ((size_t)bh * QQ + qi) * QQ * QQ;
    float* relw = g_relw + ((size_t)bh * QQ + qi) * QQ * QQ;
    for (int p = tid; p < 32 * 32; p += 256) {
        const int j = p >> 5, t = p & 31;
        const float* qrow = Qs[j];
        const float* rhr  = Rh[t];
        const float* rwr  = Rw[j - t + 31];
        float sh = 0.f, sw = 0.f;
#pragma unroll
        for (int d = 0; d < 64; d++) {
            sh += qrow[d] * rhr[d];
            sw += qrow[d] * rwr[d];
        }
        relh[(size_t)j * QQ + t] = sh;
        relw[(size_t)j * QQ + t] = sw;
    }
}

// ---------------------------------------------------------------------------
// Kernel 3: attn[bh,x,y] = 0.125 * q[bh,x,:]·k[bh,y,:] + relh + relw
// batched 1024x1024x64 GEMM, 128x128 tiles, grid (8,8,96)
// ---------------------------------------------------------------------------
__global__ __launch_bounds__(256) void k_scores() {
    __shared__ __align__(16) float As[8][128];
    __shared__ __align__(16) float Bs[8][128];
    const int tid = threadIdx.x;
    const int bh = blockIdx.z;
    const int bm = blockIdx.y * 128;
    const int bn = blockIdx.x * 128;
    const float* Qp = g_q + (size_t)bh * SS * HDM;
    const float* Kp = g_k + (size_t)bh * SS * HDM;
    const int lr = tid >> 1;
    const int lc = (tid & 1) * 4;
    const int tx = tid & 15, ty = tid >> 4;
    float acc[8][8];
#pragma unroll
    for (int i = 0; i < 8; i++)
#pragma unroll
        for (int j = 0; j < 8; j++) acc[i][j] = 0.f;

    for (int k0 = 0; k0 < HDM; k0 += 8) {
        float4 a = *(const float4*)(Qp + (size_t)(bm + lr) * HDM + k0 + lc);
        As[lc+0][lr] = a.x; As[lc+1][lr] = a.y; As[lc+2][lr] = a.z; As[lc+3][lr] = a.w;
        float4 b = *(const float4*)(Kp + (size_t)(bn + lr) * HDM + k0 + lc);
        Bs[lc+0][lr] = b.x; Bs[lc+1][lr] = b.y; Bs[lc+2][lr] = b.z; Bs[lc+3][lr] = b.w;
        __syncthreads();
#pragma unroll
        for (int k = 0; k < 8; k++) {
            float af[8], bf[8];
            *(float4*)(af)     = *(const float4*)(&As[k][ty*8]);
            *(float4*)(af + 4) = *(const float4*)(&As[k][ty*8 + 4]);
            *(float4*)(bf)     = *(const float4*)(&Bs[k][tx*8]);
            *(float4*)(bf + 4) = *(const float4*)(&Bs[k][tx*8 + 4]);
#pragma unroll
            for (int i = 0; i < 8; i++)
#pragma unroll
                for (int j = 0; j < 8; j++)
                    acc[i][j] += af[i] * bf[j];
        }
        __syncthreads();
    }

    const float* rh = g_relh + (size_t)bh * QQ * QQ * QQ;
    const float* rw = g_relw + (size_t)bh * QQ * QQ * QQ;
    float* out = g_attn + (size_t)bh * SS * SS;
#pragma unroll
    for (int i = 0; i < 8; i++) {
        const int x = bm + ty*8 + i;
        const int qi = x >> 5, qj = x & 31;
        const float* rhrow = rh + ((size_t)qi * QQ + qj) * QQ;
        const float* rwrow = rw + ((size_t)qi * QQ + qj) * QQ;
#pragma unroll
        for (int j = 0; j < 8; j++) {
            const int y = bn + tx*8 + j;
            const int ti = y >> 5, tj = y & 31;
            out[(size_t)x * SS + y] = acc[i][j] * 0.125f + rhrow[ti] + rwrow[tj];
        }
    }
}

// ---------------------------------------------------------------------------
// Kernel 4: row softmax over 1024, one block per row, float4 per thread.
// ---------------------------------------------------------------------------
__global__ __launch_bounds__(256) void k_softmax() {
    __shared__ float rm[8];
    __shared__ float rs[8];
    const size_t row = blockIdx.x;
    float* p = g_attn + row * SS;
    const int tid = threadIdx.x;
    float4 v = reinterpret_cast<const float4*>(p)[tid];

    float m = fmaxf(fmaxf(v.x, v.y), fmaxf(v.z, v.w));
#pragma unroll
    for (int o = 16; o; o >>= 1) m = fmaxf(m, __shfl_xor_sync(0xffffffffu, m, o));
    if ((tid & 31) == 0) rm[tid >> 5] = m;
    __syncthreads();
    float gm = rm[0];
#pragma unroll
    for (int w = 1; w < 8; w++) gm = fmaxf(gm, rm[w]);

    v.x = __expf(v.x - gm);
    v.y = __expf(v.y - gm);
    v.z = __expf(v.z - gm);
    v.w = __expf(v.w - gm);
    float s = v.x + v.y + v.z + v.w;
#pragma unroll
    for (int o = 16; o; o >>= 1) s += __shfl_xor_sync(0xffffffffu, s, o);
    if ((tid & 31) == 0) rs[tid >> 5] = s;
    __syncthreads();
    float gs = rs[0];
#pragma unroll
    for (int w = 1; w < 8; w++) gs += rs[w];

    const float inv = 1.0f / gs;
    v.x *= inv; v.y *= inv; v.z *= inv; v.w *= inv;
    reinterpret_cast<float4*>(p)[tid] = v;
}

// ---------------------------------------------------------------------------
// Kernel 5: ctx[b,s,h*64+d] = sum_y attn[bh,s,y] * v[bh,y,d]
// per bh: 1024x64x1024 GEMM. BM=128, BN=64, BK=16, 8x4 per thread.
// ---------------------------------------------------------------------------
__global__ __launch_bounds__(256) void k_av() {
    __shared__ __align__(16) float As[16][128];
    __shared__ __align__(16) float Bs[16][64];
    const int tid = threadIdx.x;
    const int bh = blockIdx.y;
    const int bm = blockIdx.x * 128;
    const float* Ap = g_attn + (size_t)bh * SS * SS;
    const float* Vp = g_v + (size_t)bh * SS * HDM;
    const int lrA = tid >> 1;             // 0..127
    const int lcA = (tid & 1) * 8;        // 0 or 8
    const int lrB = tid >> 4;             // 0..15
    const int lcB = (tid & 15) * 4;       // 0..60
    const int tx = tid & 15;              // N: tx*4
    const int ty = tid >> 4;              // M: ty*8
    float acc[8][4];
#pragma unroll
    for (int i = 0; i < 8; i++)
#pragma unroll
        for (int j = 0; j < 4; j++) acc[i][j] = 0.f;

    for (int k0 = 0; k0 < SS; k0 += 16) {
        const float* arow = Ap + (size_t)(bm + lrA) * SS + k0 + lcA;
        float4 a0 = *(const float4*)(arow);
        float4 a1 = *(const float4*)(arow + 4);
        As[lcA+0][lrA] = a0.x; As[lcA+1][lrA] = a0.y; As[lcA+2][lrA] = a0.z; As[lcA+3][lrA] = a0.w;
        As[lcA+4][lrA] = a1.x; As[lcA+5][lrA] = a1.y; As[lcA+6][lrA] = a1.z; As[lcA+7][lrA] = a1.w;
        *(float4*)(&Bs[lrB][lcB]) = *(const float4*)(Vp + (size_t)(k0 + lrB) * HDM + lcB);
        __syncthreads();
#pragma unroll
        for (int k = 0; k < 16; k++) {
            float af[8], bf[4];
            *(float4*)(af)     = *(const float4*)(&As[k][ty*8]);
            *(float4*)(af + 4) = *(const float4*)(&As[k][ty*8 + 4]);
            *(float4*)(bf)     = *(const float4*)(&Bs[k][tx*4]);
#pragma unroll
            for (int i = 0; i < 8; i++)
#pragma unroll
                for (int j = 0; j < 4; j++)
                    acc[i][j] += af[i] * bf[j];
        }
        __syncthreads();
    }

    const int b = bh / HH, h = bh % HH;
#pragma unroll
    for (int i = 0; i < 8; i++) {
        const int s = bm + ty*8 + i;
        float* dst = g_ctx + (size_t)(b * SS + s) * CC + h * HDM + tx * 4;
        *(float4*)dst = make_float4(acc[i][0], acc[i][1], acc[i][2], acc[i][3]);
    }
}

// ---------------------------------------------------------------------------
// Kernel 6: out = ctx @ w_out^T + b_out. M=8192, N=768, K=768.
// ---------------------------------------------------------------------------
__global__ __launch_bounds__(256) void k_proj(const float* __restrict__ W,
                                              const float* __restrict__ bias,
                                              float* __restrict__ out) {
    __shared__ __align__(16) float As[8][128];
    __shared__ __align__(16) float Bs[8][128];
    const int tid = threadIdx.x;
    const int bm = blockIdx.y * 128;
    const int bn = blockIdx.x * 128;
    const int lr = tid >> 1;
    const int lc = (tid & 1) * 4;
    const int tx = tid & 15, ty = tid >> 4;
    float acc[8][8];
#pragma unroll
    for (int i = 0; i < 8; i++)
#pragma unroll
        for (int j = 0; j < 8; j++) acc[i][j] = 0.f;

    for (int k0 = 0; k0 < CC; k0 += 8) {
        float4 a = *(const float4*)(g_ctx + (size_t)(bm + lr) * CC + k0 + lc);
        As[lc+0][lr] = a.x; As[lc+1][lr] = a.y; As[lc+2][lr] = a.z; As[lc+3][lr] = a.w;
        float4 b = *(const float4*)(W + (size_t)(bn + lr) * CC + k0 + lc);
        Bs[lc+0][lr] = b.x; Bs[lc+1][lr] = b.y; Bs[lc+2][lr] = b.z; Bs[lc+3][lr] = b.w;
        __syncthreads();
#pragma unroll
        for (int k = 0; k < 8; k++) {
            float af[8], bf[8];
            *(float4*)(af)     = *(const float4*)(&As[k][ty*8]);
            *(float4*)(af + 4) = *(const float4*)(&As[k][ty*8 + 4]);
            *(float4*)(bf)     = *(const float4*)(&Bs[k][tx*8]);
            *(float4*)(bf + 4) = *(const float4*)(&Bs[k][tx*8 + 4]);
#pragma unroll
            for (int i = 0; i < 8; i++)
#pragma unroll
                for (int j = 0; j < 8; j++)
                    acc[i][j] += af[i] * bf[j];
        }
        __syncthreads();
    }

#pragma unroll
    for (int i = 0; i < 8; i++) {
        const int m = bm + ty*8 + i;
#pragma unroll
        for (int j = 0; j < 8; j++) {
            const int n = bn + tx*8 + j;
            out[(size_t)m * CC + n] = acc[i][j] + bias[n];
        }
    }
}

// ---------------------------------------------------------------------------
extern "C" void kernel_launch(void* const* d_in, const int* in_sizes, int n_in,
                              void* d_out, int out_size) {
    const float* x     = (const float*)d_in[0];
    const float* w_qkv = (const float*)d_in[1];
    const float* w_out = (const float*)d_in[2];
    const float* b_out = (const float*)d_in[3];
    const float* rph   = (const float*)d_in[4];
    const float* rpw   = (const float*)d_in[5];
    float* out = (float*)d_out;

    k_qkv   <<<dim3(2304/128, 8192/128), 256>>>(x, w_qkv);
    k_rel   <<<dim3(BHN, QQ), 256>>>(rph, rpw);
    k_scores<<<dim3(8, 8, BHN), 256>>>();
    k_softmax<<<dim3(BHN * SS), 256>>>();
    k_av    <<<dim3(8, BHN), 256>>>();
    k_proj  <<<dim3(768/128, 8192/128), 256>>>(w_out, b_out, out);
}